// round 1
// baseline (speedup 1.0000x reference)
#include <cuda_runtime.h>
#include <cstdint>

// Decoder fused kernel: out[b,d] = (x[b,d] - diag_t[b,d]) * exp(-diag_s[b,d])
// where diag_p[b,d] = MLP_p(z[b,d,:]) taking only output column d.
// z[b,d,l] = koopman[b,l,d].   B=2048, D=64, L=64, H=512.
//
// One CTA per batch b (64 rows == the 64 d-indices). tf32 mma.sync GEMMs,
// activations resident in SMEM, weights streamed via cp.async double buffer.

namespace {

constexpr int Dn = 64;
constexpr int Hn = 512;
constexpr int LDA = 516;      // activation smem stride (floats), conflict-free frags
constexpr int LDW = 520;      // weight-chunk smem stride (floats)
constexpr int CK = 16;        // K rows per weight chunk
constexpr int NTHREADS = 256; // 8 warps: 2 (M) x 4 (N)

// floats of dynamic smem
constexpr int SMEM_A_F    = 64 * LDA;       // 33024
constexpr int SMEM_W_F    = 2 * CK * LDW;   // 16640
constexpr int SMEM_BIAS_F = Hn;             // 512
constexpr int SMEM_RED_F  = 256;
constexpr int SMEM_S_F    = 64;
constexpr int SMEM_TOTAL_F = SMEM_A_F + SMEM_W_F + SMEM_BIAS_F + SMEM_RED_F + SMEM_S_F;
constexpr int SMEM_BYTES = SMEM_TOTAL_F * 4; // 201984

__device__ __forceinline__ float tf32r(float f) {
    asm("cvt.rna.tf32.f32 %0, %0;" : "+f"(f));
    return f;
}
__device__ __forceinline__ unsigned f2tf(float f) {
    unsigned u;
    asm("cvt.rna.tf32.f32 %0, %1;" : "=r"(u) : "f"(f));
    return u;
}
__device__ __forceinline__ void mma8(float c[4], const unsigned a[4], unsigned b0, unsigned b1) {
    asm volatile(
        "mma.sync.aligned.m16n8k8.row.col.f32.tf32.tf32.f32 "
        "{%0,%1,%2,%3}, {%4,%5,%6,%7}, {%8,%9}, {%0,%1,%2,%3};"
        : "+f"(c[0]), "+f"(c[1]), "+f"(c[2]), "+f"(c[3])
        : "r"(a[0]), "r"(a[1]), "r"(a[2]), "r"(a[3]), "r"(b0), "r"(b1));
}
__device__ __forceinline__ void cp16(void* smem_dst, const void* gsrc) {
    unsigned s = (unsigned)__cvta_generic_to_shared(smem_dst);
    asm volatile("cp.async.cg.shared.global [%0], [%1], 16;" :: "r"(s), "l"(gsrc));
}
__device__ __forceinline__ void cp_commit() { asm volatile("cp.async.commit_group;"); }
template <int N>
__device__ __forceinline__ void cp_wait() { asm volatile("cp.async.wait_group %0;" :: "n"(N)); }

// accurate tanh: 1 - 2/(exp(2x)+1); __expf overflow -> inf -> result 1, underflow -> -1.
__device__ __forceinline__ float fast_tanh(float x) {
    float e = __expf(2.0f * x);
    return 1.0f - __fdividef(2.0f, e + 1.0f);
}

// copy one K-chunk (CK x 512 floats, contiguous rows in gmem) into padded smem
__device__ __forceinline__ void load_chunk(const float* __restrict__ Wg, float* dst,
                                           int c, int tid) {
    const float4* src = reinterpret_cast<const float4*>(Wg + (size_t)c * CK * Hn);
#pragma unroll
    for (int j = 0; j < (CK * Hn / 4) / NTHREADS; ++j) {  // 8
        int f4 = tid + j * NTHREADS;     // 0..2047
        int row = f4 >> 7;               // 128 float4 per 512-col row
        int col4 = f4 & 127;
        cp16(dst + row * LDW + col4 * 4, src + f4);
    }
}

// C[64,512] (+)= A[64,K] @ W[K,512];  A in sA (tf32 bits), W streamed from gmem.
template <int K>
__device__ __forceinline__ void gemm_layer(const float* __restrict__ Wg,
                                           const float* __restrict__ bias,
                                           float* sA, float* sW, float* sBias,
                                           float acc[2][16][4],
                                           int tid, int lane, int wm, int wn) {
    constexpr int NCH = K / CK;
#pragma unroll
    for (int m = 0; m < 2; ++m)
#pragma unroll
        for (int n = 0; n < 16; ++n)
#pragma unroll
            for (int q = 0; q < 4; ++q) acc[m][n][q] = 0.0f;

    for (int i = tid; i < Hn; i += NTHREADS) sBias[i] = bias[i];

    load_chunk(Wg, sW, 0, tid);
    cp_commit();

    const int g = lane >> 2;   // 0..7
    const int t4 = lane & 3;   // 0..3

#pragma unroll 1
    for (int c = 0; c < NCH; ++c) {
        if (c + 1 < NCH) {
            load_chunk(Wg, sW + ((c + 1) & 1) * CK * LDW, c + 1, tid);
            cp_commit();
            cp_wait<1>();
        } else {
            cp_wait<0>();
        }
        __syncthreads();
        const float* wb = sW + (c & 1) * CK * LDW;
#pragma unroll
        for (int s = 0; s < 2; ++s) {
            const int kk = c * CK + s * 8;
            unsigned a[2][4];
#pragma unroll
            for (int m = 0; m < 2; ++m) {
                const int row = wm * 32 + m * 16 + g;
                const float* ap = sA + row * LDA + kk + t4;
                const float* ap8 = ap + 8 * LDA;
                // m16n8k8 tf32 A frag: a0:(g,t4) a1:(g+8,t4) a2:(g,t4+4) a3:(g+8,t4+4)
                a[m][0] = __float_as_uint(ap[0]);
                a[m][1] = __float_as_uint(ap8[0]);
                a[m][2] = __float_as_uint(ap[4]);
                a[m][3] = __float_as_uint(ap8[4]);
            }
            const float* bp0 = wb + (s * 8 + t4) * LDW + wn * 128 + g;
#pragma unroll
            for (int n = 0; n < 16; ++n) {
                // B frag: b0:(row=t4, col=g)  b1:(row=t4+4, col=g)
                unsigned b0 = f2tf(bp0[n * 8]);
                unsigned b1 = f2tf(bp0[n * 8 + 4 * LDW]);
                mma8(acc[0][n], a[0], b0, b1);
                mma8(acc[1][n], a[1], b0, b1);
            }
        }
        __syncthreads();
    }
}

// h = tanh(acc + bias) written back to sA as tf32 bits
__device__ __forceinline__ void store_h(const float acc[2][16][4], float* sA,
                                        const float* sBias, int lane, int wm, int wn) {
    const int g = lane >> 2;
    const int t4 = lane & 3;
#pragma unroll
    for (int m = 0; m < 2; ++m) {
        const int row0 = wm * 32 + m * 16 + g;
#pragma unroll
        for (int n = 0; n < 16; ++n) {
            const int col = wn * 128 + n * 8 + t4 * 2;
            const float b0 = sBias[col], b1 = sBias[col + 1];
            sA[row0 * LDA + col]           = tf32r(fast_tanh(acc[m][n][0] + b0));
            sA[row0 * LDA + col + 1]       = tf32r(fast_tanh(acc[m][n][1] + b1));
            sA[(row0 + 8) * LDA + col]     = tf32r(fast_tanh(acc[m][n][2] + b0));
            sA[(row0 + 8) * LDA + col + 1] = tf32r(fast_tanh(acc[m][n][3] + b1));
        }
    }
}

__global__ __launch_bounds__(NTHREADS, 1)
void decoder_kernel(const float* __restrict__ x, const float* __restrict__ koop,
                    const float* __restrict__ sW1, const float* __restrict__ sb1,
                    const float* __restrict__ sW2, const float* __restrict__ sb2,
                    const float* __restrict__ sW3, const float* __restrict__ sb3,
                    const float* __restrict__ sW4, const float* __restrict__ sb4,
                    const float* __restrict__ tW1, const float* __restrict__ tb1,
                    const float* __restrict__ tW2, const float* __restrict__ tb2,
                    const float* __restrict__ tW3, const float* __restrict__ tb3,
                    const float* __restrict__ tW4, const float* __restrict__ tb4,
                    float* __restrict__ out) {
    extern __shared__ float smem[];
    float* sA = smem;
    float* sW = sA + SMEM_A_F;
    float* sBias = sW + SMEM_W_F;
    float* sRed = sBias + SMEM_BIAS_F;
    float* sS = sRed + SMEM_RED_F;

    const int tid = threadIdx.x;
    const int lane = tid & 31;
    const int wid = tid >> 5;
    const int wm = wid >> 2;  // 0..1
    const int wn = wid & 3;   // 0..3
    const int b = blockIdx.x;

    float acc[2][16][4];

#pragma unroll 1
    for (int mlp = 0; mlp < 2; ++mlp) {
        const float* W1 = mlp ? tW1 : sW1;  const float* b1 = mlp ? tb1 : sb1;
        const float* W2 = mlp ? tW2 : sW2;  const float* b2 = mlp ? tb2 : sb2;
        const float* W3 = mlp ? tW3 : sW3;  const float* b3 = mlp ? tb3 : sb3;
        const float* W4 = mlp ? tW4 : sW4;  const float* b4 = mlp ? tb4 : sb4;

        // load z (rows = d, cols = l): sA[d][l] = koopman[b, l, d]
        const float* kb = koop + (size_t)b * 4096;
        for (int i = tid; i < 4096; i += NTHREADS) {
            const int l = i >> 6, d = i & 63;
            sA[d * LDA + l] = tf32r(kb[i]);
        }
        // visibility guaranteed by gemm_layer's internal barrier before A-reads

        gemm_layer<64>(W1, b1, sA, sW, sBias, acc, tid, lane, wm, wn);
        store_h(acc, sA, sBias, lane, wm, wn);
        __syncthreads();  // protect sBias before next layer overwrites it
        gemm_layer<512>(W2, b2, sA, sW, sBias, acc, tid, lane, wm, wn);
        store_h(acc, sA, sBias, lane, wm, wn);
        __syncthreads();
        gemm_layer<512>(W3, b3, sA, sW, sBias, acc, tid, lane, wm, wn);
        store_h(acc, sA, sBias, lane, wm, wn);
        __syncthreads();  // h3 fully written before layer-4 reads

        // layer 4: only the diagonal — row r dots W4[:, r]
        const int r = tid & 63;
        const int p = tid >> 6;  // 4 partial sums per row
        float a4 = 0.0f;
        const float* hrow = sA + r * LDA + p * 128;
        const float* wcol = W4 + (size_t)(p * 128) * 64 + r;
#pragma unroll 8
        for (int i = 0; i < 128; ++i)
            a4 += hrow[i] * __ldg(wcol + (size_t)i * 64);
        sRed[p * 64 + r] = a4;
        __syncthreads();
        if (tid < 64) {
            const float v = sRed[tid] + sRed[64 + tid] + sRed[128 + tid] + sRed[192 + tid]
                          + b4[tid];
            if (mlp == 0) {
                sS[tid] = v;  // s diagonal
            } else {
                const size_t o = (size_t)b * 64 + tid;
                out[o] = (x[o] - v) * __expf(-sS[tid]);
            }
        }
        __syncthreads();
    }
}

}  // namespace

extern "C" void kernel_launch(void* const* d_in, const int* in_sizes, int n_in,
                              void* d_out, int out_size) {
    (void)in_sizes; (void)n_in; (void)out_size;
    const float* x    = (const float*)d_in[0];
    const float* koop = (const float*)d_in[1];
    const float* sW1 = (const float*)d_in[2];
    const float* sb1 = (const float*)d_in[3];
    const float* sW2 = (const float*)d_in[4];
    const float* sb2 = (const float*)d_in[5];
    const float* sW3 = (const float*)d_in[6];
    const float* sb3 = (const float*)d_in[7];
    const float* sW4 = (const float*)d_in[8];
    const float* sb4 = (const float*)d_in[9];
    const float* tW1 = (const float*)d_in[10];
    const float* tb1 = (const float*)d_in[11];
    const float* tW2 = (const float*)d_in[12];
    const float* tb2 = (const float*)d_in[13];
    const float* tW3 = (const float*)d_in[14];
    const float* tb3 = (const float*)d_in[15];
    const float* tW4 = (const float*)d_in[16];
    const float* tb4 = (const float*)d_in[17];
    float* out = (float*)d_out;

    cudaFuncSetAttribute(decoder_kernel, cudaFuncAttributeMaxDynamicSharedMemorySize,
                         SMEM_BYTES);
    decoder_kernel<<<2048, NTHREADS, SMEM_BYTES>>>(
        x, koop, sW1, sb1, sW2, sb2, sW3, sb3, sW4, sb4,
        tW1, tb1, tW2, tb2, tW3, tb3, tW4, tb4, out);
}

// round 2
// speedup vs baseline: 1.1976x; 1.1976x over previous
#include <cuda_runtime.h>
#include <cstdint>

// Decoder fused kernel: out[b,d] = (x[b,d] - diag_t[b,d]) * exp(-diag_s[b,d])
// diag_p[b,d] = column d of MLP_p(z[b,d,:]);  z[b,d,l] = koopman[b,l,d].
// B=2048, D=64, L=64, H=512.
//
// R1: prep kernels pre-round weights to tf32 AND reshuffle into an
// mma-fragment-major blob (float4 per thread per 2 n-tiles) in __device__
// scratch. Main kernel: 512 threads (2M x 8N warps), inner loop has zero CVT,
// vectorized B loads.

namespace {

constexpr int Hn = 512;
constexpr int LDA = 516;      // activation smem stride (floats)
constexpr int CK = 16;        // K rows per weight chunk
constexpr int CHUNK_F = CK * Hn;  // 8192 floats per chunk blob
constexpr int NTHREADS = 512; // 16 warps: 2 (M) x 8 (N)

// blob offsets (floats): mlp0 L1,L2,L3 then mlp1 L1,L2,L3
__device__ float g_wblob[1114112];
__constant__ int c_blob_off[6] = {0, 32768, 294912, 557056, 589824, 851968};

// dynamic smem (floats)
constexpr int SMEM_A_F    = 64 * LDA;        // 33024
constexpr int SMEM_W_F    = 2 * CHUNK_F;     // 16384
constexpr int SMEM_BIAS_F = Hn;              // 512
constexpr int SMEM_RED_F  = 512;
constexpr int SMEM_S_F    = 64;
constexpr int SMEM_BYTES = (SMEM_A_F + SMEM_W_F + SMEM_BIAS_F + SMEM_RED_F + SMEM_S_F) * 4;

__device__ __forceinline__ float tf32r(float f) {
    asm("cvt.rna.tf32.f32 %0, %0;" : "+f"(f));
    return f;
}
__device__ __forceinline__ void mma8(float c[4], const unsigned a[4], unsigned b0, unsigned b1) {
    asm volatile(
        "mma.sync.aligned.m16n8k8.row.col.f32.tf32.tf32.f32 "
        "{%0,%1,%2,%3}, {%4,%5,%6,%7}, {%8,%9}, {%0,%1,%2,%3};"
        : "+f"(c[0]), "+f"(c[1]), "+f"(c[2]), "+f"(c[3])
        : "r"(a[0]), "r"(a[1]), "r"(a[2]), "r"(a[3]), "r"(b0), "r"(b1));
}
__device__ __forceinline__ void cp16(void* smem_dst, const void* gsrc) {
    unsigned s = (unsigned)__cvta_generic_to_shared(smem_dst);
    asm volatile("cp.async.cg.shared.global [%0], [%1], 16;" :: "r"(s), "l"(gsrc));
}
__device__ __forceinline__ void cp_commit() { asm volatile("cp.async.commit_group;"); }
template <int N>
__device__ __forceinline__ void cp_wait() { asm volatile("cp.async.wait_group %0;" :: "n"(N)); }

__device__ __forceinline__ float fast_tanh(float x) {
    float e = __expf(2.0f * x);
    return 1.0f - __fdividef(2.0f, e + 1.0f);
}

// ---------- prep: W[K,512] fp32 -> tf32 fragment blob ----------
// blob element e (within layer): q=e&3, lane=(e>>2)&31, n2=(e>>7)&3,
// wn=(e>>9)&7, s=(e>>12)&1, c=e>>13.
// k = c*16 + s*8 + (lane&3) + (q&1)*4 ; col = wn*64 + (2*n2+(q>>1))*8 + (lane>>2)
__global__ void prep_kernel(const float* __restrict__ W, int slot, int total) {
    int e = blockIdx.x * blockDim.x + threadIdx.x;
    if (e >= total) return;
    const int q = e & 3;
    const int lane = (e >> 2) & 31;
    const int n2 = (e >> 7) & 3;
    const int wn = (e >> 9) & 7;
    const int s = (e >> 12) & 1;
    const int c = e >> 13;
    const int k = c * 16 + s * 8 + (lane & 3) + (q & 1) * 4;
    const int col = wn * 64 + (2 * n2 + (q >> 1)) * 8 + (lane >> 2);
    g_wblob[c_blob_off[slot] + e] = tf32r(W[k * Hn + col]);
}

// ---------- main ----------
__device__ __forceinline__ void load_chunk(const float* __restrict__ Wg, float* dst,
                                           int c, int tid) {
    const float4* src = reinterpret_cast<const float4*>(Wg + (size_t)c * CHUNK_F);
#pragma unroll
    for (int j = 0; j < (CHUNK_F / 4) / NTHREADS; ++j) {  // 4
        int f4 = tid + j * NTHREADS;
        cp16(dst + f4 * 4, src + f4);
    }
}

template <int K>
__device__ __forceinline__ void gemm_layer(const float* __restrict__ Wg,
                                           const float* __restrict__ bias,
                                           float* sA, float* sW, float* sBias,
                                           float acc[2][8][4],
                                           int tid, int lane, int wm, int wn) {
    constexpr int NCH = K / CK;
#pragma unroll
    for (int m = 0; m < 2; ++m)
#pragma unroll
        for (int n = 0; n < 8; ++n)
#pragma unroll
            for (int q = 0; q < 4; ++q) acc[m][n][q] = 0.0f;

    if (tid < Hn) sBias[tid] = bias[tid];

    load_chunk(Wg, sW, 0, tid);
    cp_commit();

    const int g = lane >> 2;
    const int t4 = lane & 3;

#pragma unroll 1
    for (int c = 0; c < NCH; ++c) {
        if (c + 1 < NCH) {
            load_chunk(Wg, sW + ((c + 1) & 1) * CHUNK_F, c + 1, tid);
            cp_commit();
            cp_wait<1>();
        } else {
            cp_wait<0>();
        }
        __syncthreads();
        const float* wb = sW + (c & 1) * CHUNK_F;
#pragma unroll
        for (int s = 0; s < 2; ++s) {
            const int kk = c * CK + s * 8;
            unsigned a[2][4];
#pragma unroll
            for (int m = 0; m < 2; ++m) {
                const int row = wm * 32 + m * 16 + g;
                const float* ap = sA + row * LDA + kk + t4;
                const float* ap8 = ap + 8 * LDA;
                a[m][0] = __float_as_uint(ap[0]);
                a[m][1] = __float_as_uint(ap8[0]);
                a[m][2] = __float_as_uint(ap[4]);
                a[m][3] = __float_as_uint(ap8[4]);
            }
            const float4* bp = reinterpret_cast<const float4*>(
                                   wb + (size_t)((s * 8 + wn) * 4) * 128) + lane;
#pragma unroll
            for (int n2 = 0; n2 < 4; ++n2) {
                const float4 bv = bp[n2 * 32];
                const unsigned b0 = __float_as_uint(bv.x);
                const unsigned b1 = __float_as_uint(bv.y);
                const unsigned b2 = __float_as_uint(bv.z);
                const unsigned b3 = __float_as_uint(bv.w);
                mma8(acc[0][2 * n2], a[0], b0, b1);
                mma8(acc[1][2 * n2], a[1], b0, b1);
                mma8(acc[0][2 * n2 + 1], a[0], b2, b3);
                mma8(acc[1][2 * n2 + 1], a[1], b2, b3);
            }
        }
        __syncthreads();
    }
}

__device__ __forceinline__ void store_h(const float acc[2][8][4], float* sA,
                                        const float* sBias, int lane, int wm, int wn) {
    const int g = lane >> 2;
    const int t4 = lane & 3;
#pragma unroll
    for (int m = 0; m < 2; ++m) {
        const int row0 = wm * 32 + m * 16 + g;
#pragma unroll
        for (int n = 0; n < 8; ++n) {
            const int col = wn * 64 + n * 8 + t4 * 2;
            const float b0 = sBias[col], b1 = sBias[col + 1];
            sA[row0 * LDA + col]           = tf32r(fast_tanh(acc[m][n][0] + b0));
            sA[row0 * LDA + col + 1]       = tf32r(fast_tanh(acc[m][n][1] + b1));
            sA[(row0 + 8) * LDA + col]     = tf32r(fast_tanh(acc[m][n][2] + b0));
            sA[(row0 + 8) * LDA + col + 1] = tf32r(fast_tanh(acc[m][n][3] + b1));
        }
    }
}

__global__ __launch_bounds__(NTHREADS, 1)
void decoder_kernel(const float* __restrict__ x, const float* __restrict__ koop,
                    const float* __restrict__ sb1, const float* __restrict__ sb2,
                    const float* __restrict__ sb3,
                    const float* __restrict__ sW4, const float* __restrict__ sb4,
                    const float* __restrict__ tb1, const float* __restrict__ tb2,
                    const float* __restrict__ tb3,
                    const float* __restrict__ tW4, const float* __restrict__ tb4,
                    float* __restrict__ out) {
    extern __shared__ float smem[];
    float* sA = smem;
    float* sW = sA + SMEM_A_F;
    float* sBias = sW + SMEM_W_F;
    float* sRed = sBias + SMEM_BIAS_F;
    float* sS = sRed + SMEM_RED_F;

    const int tid = threadIdx.x;
    const int lane = tid & 31;
    const int wid = tid >> 5;
    const int wm = wid >> 3;  // 0..1
    const int wn = wid & 7;   // 0..7
    const int b = blockIdx.x;

    float acc[2][8][4];

#pragma unroll 1
    for (int mlp = 0; mlp < 2; ++mlp) {
        const float* W1 = g_wblob + c_blob_off[mlp * 3 + 0];
        const float* W2 = g_wblob + c_blob_off[mlp * 3 + 1];
        const float* W3 = g_wblob + c_blob_off[mlp * 3 + 2];
        const float* b1 = mlp ? tb1 : sb1;
        const float* b2 = mlp ? tb2 : sb2;
        const float* b3 = mlp ? tb3 : sb3;
        const float* W4 = mlp ? tW4 : sW4;
        const float* b4 = mlp ? tb4 : sb4;

        // z load: sA[d][l] = koopman[b, l, d]
        const float* kb = koop + (size_t)b * 4096;
        for (int i = tid; i < 4096; i += NTHREADS) {
            const int l = i >> 6, d = i & 63;
            sA[d * LDA + l] = tf32r(kb[i]);
        }
        // first __syncthreads inside gemm_layer covers visibility

        gemm_layer<64>(W1, b1, sA, sW, sBias, acc, tid, lane, wm, wn);
        store_h(acc, sA, sBias, lane, wm, wn);
        __syncthreads();
        gemm_layer<512>(W2, b2, sA, sW, sBias, acc, tid, lane, wm, wn);
        store_h(acc, sA, sBias, lane, wm, wn);
        __syncthreads();
        gemm_layer<512>(W3, b3, sA, sW, sBias, acc, tid, lane, wm, wn);
        store_h(acc, sA, sBias, lane, wm, wn);
        __syncthreads();

        // layer 4 diagonal: row r dots W4[:, r]; 8 partials per row
        const int r = tid & 63;
        const int p = tid >> 6;  // 0..7
        float a4 = 0.0f;
        const float* hrow = sA + r * LDA + p * 64;
        const float* wcol = W4 + (size_t)(p * 64) * 64 + r;
#pragma unroll 8
        for (int i = 0; i < 64; ++i)
            a4 += hrow[i] * __ldg(wcol + (size_t)i * 64);
        sRed[p * 64 + r] = a4;
        __syncthreads();
        if (tid < 64) {
            float v = b4[tid];
#pragma unroll
            for (int p2 = 0; p2 < 8; ++p2) v += sRed[p2 * 64 + tid];
            if (mlp == 0) {
                sS[tid] = v;
            } else {
                const size_t o = (size_t)b * 64 + tid;
                out[o] = (x[o] - v) * __expf(-sS[tid]);
            }
        }
        __syncthreads();
    }
}

}  // namespace

extern "C" void kernel_launch(void* const* d_in, const int* in_sizes, int n_in,
                              void* d_out, int out_size) {
    (void)in_sizes; (void)n_in; (void)out_size;
    const float* x    = (const float*)d_in[0];
    const float* koop = (const float*)d_in[1];
    const float* sW1 = (const float*)d_in[2];
    const float* sb1 = (const float*)d_in[3];
    const float* sW2 = (const float*)d_in[4];
    const float* sb2 = (const float*)d_in[5];
    const float* sW3 = (const float*)d_in[6];
    const float* sb3 = (const float*)d_in[7];
    const float* sW4 = (const float*)d_in[8];
    const float* sb4 = (const float*)d_in[9];
    const float* tW1 = (const float*)d_in[10];
    const float* tb1 = (const float*)d_in[11];
    const float* tW2 = (const float*)d_in[12];
    const float* tb2 = (const float*)d_in[13];
    const float* tW3 = (const float*)d_in[14];
    const float* tb3 = (const float*)d_in[15];
    const float* tW4 = (const float*)d_in[16];
    const float* tb4 = (const float*)d_in[17];
    float* out = (float*)d_out;

    // prep: tf32-round + fragment-shuffle the 6 hidden-layer weight matrices
    const float* srcs[6] = {sW1, sW2, sW3, tW1, tW2, tW3};
    const int sizes[6] = {32768, 262144, 262144, 32768, 262144, 262144};
    for (int i = 0; i < 6; ++i)
        prep_kernel<<<(sizes[i] + 255) / 256, 256>>>(srcs[i], i, sizes[i]);

    cudaFuncSetAttribute(decoder_kernel, cudaFuncAttributeMaxDynamicSharedMemorySize,
                         SMEM_BYTES);
    decoder_kernel<<<2048, NTHREADS, SMEM_BYTES>>>(
        x, koop, sb1, sb2, sb3, sW4, sb4,
        tb1, tb2, tb3, tW4, tb4, out);
}